// round 5
// baseline (speedup 1.0000x reference)
#include <cuda_runtime.h>
#include <math_constants.h>

#define NF 8
#define NQ 300
#define HH 96
#define WW 96
#define HW (HH*WW)        // 9216
#define FHW (NF*HW)       // 73728
#define ALPHA_C 0.25f
#define EPSV 1e-8f

__device__ float g_tgtx[2][NF*HH];     // max over w per (f,h)
__device__ float g_tgty[2][NF*WW];     // max over h per (f,w)
__device__ float g_partial[16][3];     // per (b,f): [tsum, sum(tgtx), sum(tgty)]
__device__ uint2 g_meta[16][HH*3];     // per (b,f,row,chunk): {tmask bits, vpad bits}

__device__ __forceinline__ float tanh_hw(float x) {
    float y;
    asm("tanh.approx.f32 %0, %1;" : "=f"(y) : "f"(x));
    return y;
}
__device__ __forceinline__ float sigmoid_hw(float x) {
    return fmaf(0.5f, tanh_hw(0.5f * x), 0.5f);
}
__device__ __forceinline__ float sigmoid_fast(float x) {   // exact version (epilogue)
    float a = fabsf(x);
    float u = __expf(-a);
    float r = __fdividef(1.0f, 1.0f + u);
    return (x >= 0.0f) ? r : u * r;
}

__device__ __forceinline__ float warp_sum(float v) {
    #pragma unroll
    for (int o = 16; o; o >>= 1) v += __shfl_xor_sync(0xffffffff, v, o);
    return v;
}
__device__ __forceinline__ float warp_max(float v) {
    #pragma unroll
    for (int o = 16; o; o >>= 1) v = fmaxf(v, __shfl_xor_sync(0xffffffff, v, o));
    return v;
}

// ---------------------------------------------------------------------------
// Prep: one block per (b,f). 384 threads = 12 warps; warp owns 8 rows.
// ---------------------------------------------------------------------------
__global__ __launch_bounds__(384) void prep_kernel(
    const float* __restrict__ tmask, const unsigned char* __restrict__ vpad)
{
    int bf = blockIdx.x;            // 0..15
    int b = bf >> 3, f = bf & 7;
    int tid = threadIdx.x;
    int wp = tid >> 5, lane = tid & 31;
    const float* base = tmask + (size_t)bf * HW;
    const unsigned char* vb = vpad + (size_t)b * HW;

    __shared__ float colPart[12][3][32];
    __shared__ float warpRM[12];
    __shared__ float warpTS[12];
    __shared__ float colFinal[96];

    float cm0 = -CUDART_INF_F, cm1 = -CUDART_INF_F, cm2 = -CUDART_INF_F;
    float rm_sum = 0.0f, t_sum = 0.0f;

    #pragma unroll 2
    for (int r = 0; r < 8; ++r) {
        int row = wp * 8 + r;
        const float* rp = base + row * WW;
        const unsigned char* vr = vb + row * WW;
        float v0 = rp[lane], v1 = rp[32 + lane], v2 = rp[64 + lane];
        unsigned char q0 = vr[lane], q1 = vr[32 + lane], q2 = vr[64 + lane];
        unsigned t0 = __ballot_sync(0xffffffff, v0 != 0.0f);
        unsigned t1 = __ballot_sync(0xffffffff, v1 != 0.0f);
        unsigned t2 = __ballot_sync(0xffffffff, v2 != 0.0f);
        unsigned p0 = __ballot_sync(0xffffffff, q0 != 0);
        unsigned p1 = __ballot_sync(0xffffffff, q1 != 0);
        unsigned p2 = __ballot_sync(0xffffffff, q2 != 0);
        if (lane == 0) {
            g_meta[bf][row * 3 + 0] = make_uint2(t0, p0);
            g_meta[bf][row * 3 + 1] = make_uint2(t1, p1);
            g_meta[bf][row * 3 + 2] = make_uint2(t2, p2);
        }
        float rm = warp_max(fmaxf(fmaxf(v0, v1), v2));
        if (lane == 0) { g_tgtx[b][f * HH + row] = rm; rm_sum += rm; }
        t_sum += v0 + v1 + v2;
        cm0 = fmaxf(cm0, v0); cm1 = fmaxf(cm1, v1); cm2 = fmaxf(cm2, v2);
    }
    colPart[wp][0][lane] = cm0;
    colPart[wp][1][lane] = cm1;
    colPart[wp][2][lane] = cm2;
    float ts = warp_sum(t_sum);
    if (lane == 0) { warpTS[wp] = ts; warpRM[wp] = rm_sum; }
    __syncthreads();

    if (tid < 96) {
        int c = tid >> 5, l = tid & 31;
        float m = -CUDART_INF_F;
        #pragma unroll
        for (int w = 0; w < 12; ++w) m = fmaxf(m, colPart[w][c][l]);
        g_tgty[b][f * WW + tid] = m;
        colFinal[tid] = m;
    }
    __syncthreads();
    if (tid == 0) {
        float tsum = 0, txs = 0, tys = 0;
        #pragma unroll
        for (int i = 0; i < 12; ++i) { tsum += warpTS[i]; txs += warpRM[i]; }
        for (int i = 0; i < 96; ++i) tys += colFinal[i];
        g_partial[bf][0] = tsum; g_partial[bf][1] = txs; g_partial[bf][2] = tys;
    }
}

// ---------------------------------------------------------------------------
// Main cost kernel: one block per (b, q). 384 threads = 12 warps, occ 4.
// Warp wp owns rows 8*wp..8*wp+7 of every frame; lane l covers cols {l,32+l,64+l}.
// ---------------------------------------------------------------------------
__global__ __launch_bounds__(384, 4) void cost_kernel(
    const float* __restrict__ logits,   // (2,8,300,1)
    const float* __restrict__ boxes,    // (2,8,300,4)
    const float* __restrict__ masks,    // (2,8,300,96,96)
    const float* __restrict__ tbox,     // (2,8,4)
    const int*   __restrict__ tvalid,   // (2,8)
    float* __restrict__ C)              // (2,300)
{
    int blk = blockIdx.x;
    int b = blk / NQ, q = blk % NQ;
    int tid = threadIdx.x;
    int warp = tid >> 5, lane = tid & 31;

    __shared__ float rowFinal[NF * HH];           // 3 KB
    __shared__ float colAll[NF * 3 * 384];        // 36 KB: [f][chunk][warp][lane]
    __shared__ float red[12][7];

    float facc = 0.0f, nacc = 0.0f, sacc = 0.0f;

    for (int f = 0; f < NF; ++f) {
        const float* mb = masks + (size_t)((b * NF + f) * NQ + q) * HW + lane;
        const uint2* mt = g_meta[b * NF + f];
        float c0 = -CUDART_INF_F, c1 = -CUDART_INF_F, c2 = -CUDART_INF_F;
        for (int r = 0; r < 8; ++r) {
            int row = warp * 8 + r;
            uint2 m0 = mt[row * 3 + 0];
            uint2 m1 = mt[row * 3 + 1];
            uint2 m2 = mt[row * 3 + 2];
            const float* rp = mb + row * WW;
            float x0 = rp[0], x1 = rp[32], x2 = rp[64];
            if ((m0.y >> lane) & 1) x0 = 0.0f;
            if ((m1.y >> lane) & 1) x1 = 0.0f;
            if ((m2.y >> lane) & 1) x2 = 0.0f;

            #pragma unroll
            for (int c = 0; c < 3; ++c) {
                float x = (c == 0) ? x0 : (c == 1) ? x1 : x2;
                unsigned tw = (c == 0) ? m0.x : (c == 1) ? m1.x : m2.x;
                bool tb = (tw >> lane) & 1;
                float p = sigmoid_hw(x);                 // 1 MUFU
                float omp_ = 1.0f - p;
                float pa = fmaxf(p, omp_);               // sigmoid(|x|)
                float lg = -__logf(pa);                  // log1p(exp(-|x|)), 1 MUFU
                float ce = fmaxf(tb ? -x : x, 0.0f) + lg;
                float omp = tb ? omp_ : p;               // 1 - p_t
                float at = tb ? 0.25f : 0.75f;
                facc = fmaf(at * ce * omp, omp, facc);
                sacc += p;
                if (tb) nacc += p;
            }
            c0 = fmaxf(c0, x0); c1 = fmaxf(c1, x1); c2 = fmaxf(c2, x2);
            float rm = warp_max(fmaxf(fmaxf(x0, x1), x2));
            if (lane == 0) rowFinal[f * HH + row] = rm;
        }
        colAll[((f * 3 + 0) * 12 + warp) * 32 + lane] = c0;
        colAll[((f * 3 + 1) * 12 + warp) * 32 + lane] = c1;
        colAll[((f * 3 + 2) * 12 + warp) * 32 + lane] = c2;
    }
    __syncthreads();

    // projection dice partials: 768 rows + 768 cols, 2 each per thread
    float sx = 0, nx = 0, sy = 0, ny = 0;
    #pragma unroll
    for (int j = tid; j < NF * HH; j += 384) {
        float px = sigmoid_fast(rowFinal[j]);
        sx += px; nx += px * g_tgtx[b][j];
        int f = j / WW, w = j % WW;
        int c = w >> 5, l = w & 31;
        const float* cp = &colAll[((f * 3 + c) * 12) * 32 + l];
        float m = cp[0];
        #pragma unroll
        for (int wp = 1; wp < 12; ++wp) m = fmaxf(m, cp[wp * 32]);
        float py = sigmoid_fast(m);
        sy += py; ny += py * g_tgty[b][j];
    }

    float v0 = warp_sum(facc), v1 = warp_sum(nacc), v2 = warp_sum(sacc);
    float v3 = warp_sum(sx),   v4 = warp_sum(nx);
    float v5 = warp_sum(sy),   v6 = warp_sum(ny);
    if (lane == 0) {
        red[warp][0] = v0; red[warp][1] = v1; red[warp][2] = v2;
        red[warp][3] = v3; red[warp][4] = v4; red[warp][5] = v5; red[warp][6] = v6;
    }
    __syncthreads();

    if (tid == 0) {
        float t0=0,t1=0,t2=0,t3=0,t4=0,t5=0,t6=0;
        #pragma unroll
        for (int i = 0; i < 12; ++i) {
            t0 += red[i][0]; t1 += red[i][1]; t2 += red[i][2];
            t3 += red[i][3]; t4 += red[i][4]; t5 += red[i][5]; t6 += red[i][6];
        }
        float tsum = 0, txs = 0, tys = 0;
        #pragma unroll
        for (int f = 0; f < NF; ++f) {
            tsum += g_partial[b * NF + f][0];
            txs  += g_partial[b * NF + f][1];
            tys  += g_partial[b * NF + f][2];
        }
        float cost_mask = t0 / (float)FHW;
        float cost_dice = -((2.0f * t1 + 1.0f) / (t2 + tsum + 1.0f));
        float dx = (2.0f * t4 + 1.0f) / (t3 + txs + 1.0f);
        float dy = (2.0f * t6 + 1.0f) / (t5 + tys + 1.0f);
        float cost_proj = -0.5f * (dy + dx);

        float cls = 0, wsum = 0, bbox = 0, giou = 0;
        #pragma unroll
        for (int f = 0; f < NF; ++f) {
            float lg = logits[(b * NF + f) * NQ + q];
            float p = sigmoid_fast(lg);
            float neg = (1.0f - ALPHA_C) * p * p * (-__logf(1.0f - p + EPSV));
            float pos = ALPHA_C * (1.0f - p) * (1.0f - p) * (-__logf(p + EPSV));
            float wv = (tvalid[b * NF + f] != 0) ? 1.0f : 0.0f;
            cls += (pos - neg) * wv; wsum += wv;

            const float* bx = boxes + (size_t)((b * NF + f) * NQ + q) * 4;
            const float* tx = tbox + (size_t)(b * NF + f) * 4;
            bbox += fabsf(bx[0]-tx[0]) + fabsf(bx[1]-tx[1]) + fabsf(bx[2]-tx[2]) + fabsf(bx[3]-tx[3]);

            float sx0 = bx[0]-0.5f*bx[2], sy0 = bx[1]-0.5f*bx[3];
            float sx1 = bx[0]+0.5f*bx[2], sy1 = bx[1]+0.5f*bx[3];
            float tx0 = tx[0]-0.5f*tx[2], ty0 = tx[1]-0.5f*tx[3];
            float tx1 = tx[0]+0.5f*tx[2], ty1 = tx[1]+0.5f*tx[3];
            float a1 = (sx1-sx0)*(sy1-sy0);
            float a2 = (tx1-tx0)*(ty1-ty0);
            float iw = fmaxf(fminf(sx1,tx1) - fmaxf(sx0,tx0), 0.0f);
            float ih = fmaxf(fminf(sy1,ty1) - fmaxf(sy0,ty0), 0.0f);
            float inter = iw * ih;
            float uni = a1 + a2 - inter;
            float iou = inter / uni;
            float cw = fmaxf(fmaxf(sx1,tx1) - fminf(sx0,tx0), 0.0f);
            float ch = fmaxf(fmaxf(sy1,ty1) - fminf(sy0,ty0), 0.0f);
            float ac = cw * ch;
            giou += -(iou - (ac - uni) / ac);
        }
        float cost_class = cls / wsum;
        float cost_bbox  = bbox * (1.0f / NF);
        float cost_giou  = giou * (1.0f / NF);

        C[b * NQ + q] = cost_class + cost_bbox + cost_giou + cost_mask + cost_dice + cost_proj;
    }
}

// ---------------------------------------------------------------------------
// Argmin over queries per batch + tail writes. grid=2, block=256
// ---------------------------------------------------------------------------
__global__ void argmin_kernel(const float* __restrict__ C, float* __restrict__ out, int out_size) {
    int b = blockIdx.x;
    int tid = threadIdx.x;
    float best = CUDART_INF_F; int bi = NQ;
    for (int q = tid; q < NQ; q += blockDim.x) {
        float v = C[b * NQ + q];
        if (v < best || (v == best && q < bi)) { best = v; bi = q; }
    }
    #pragma unroll
    for (int o = 16; o; o >>= 1) {
        float ov = __shfl_down_sync(0xffffffff, best, o);
        int   oi = __shfl_down_sync(0xffffffff, bi,   o);
        if (ov < best || (ov == best && oi < bi)) { best = ov; bi = oi; }
    }
    __shared__ float sv[8]; __shared__ int si[8];
    int wid = tid >> 5, lane = tid & 31;
    if (lane == 0) { sv[wid] = best; si[wid] = bi; }
    __syncthreads();
    if (tid == 0) {
        int nw = blockDim.x >> 5;
        for (int i = 1; i < nw; ++i) {
            if (sv[i] < best || (sv[i] == best && si[i] < bi)) { best = sv[i]; bi = si[i]; }
        }
        if (out_size >= 608) {
            long long* op = (long long*)(out + 600);
            op[b] = (long long)bi;
            op[2 + b] = 0ll;
            if (b == 0) for (int i = 608; i < out_size; ++i) out[i] = 0.0f;
        } else if (out_size >= 604) {
            out[600 + b] = (float)bi;
            out[602 + b] = 0.0f;
            if (b == 0) for (int i = 604; i < out_size; ++i) out[i] = 0.0f;
        } else {
            if (b == 0) for (int i = 600; i < out_size; ++i) out[i] = 0.0f;
        }
    }
}

extern "C" void kernel_launch(void* const* d_in, const int* in_sizes, int n_in,
                              void* d_out, int out_size) {
    const float* logits = (const float*)d_in[0];
    const float* boxes  = (const float*)d_in[1];
    const float* masks  = (const float*)d_in[2];
    const float* tmask  = (const float*)d_in[3];
    const float* tbox   = (const float*)d_in[4];
    const int*   tvalid = (const int*)d_in[5];
    const unsigned char* vpad = (const unsigned char*)d_in[6];
    float* out = (float*)d_out;

    prep_kernel<<<16, 384>>>(tmask, vpad);
    cost_kernel<<<2 * NQ, 384>>>(logits, boxes, masks, tbox, tvalid, out);
    argmin_kernel<<<2, 256>>>(out, out, out_size);
}

// round 6
// speedup vs baseline: 1.2680x; 1.2680x over previous
#include <cuda_runtime.h>
#include <math_constants.h>

#define NF 8
#define NQ 300
#define HH 96
#define WW 96
#define HW (HH*WW)        // 9216
#define FHW (NF*HW)       // 73728
#define ALPHA_C 0.25f
#define EPSV 1e-8f

__device__ float g_tgtx[2][NF*HH];     // max over w per (f,h)
__device__ float g_tgty[2][NF*WW];     // max over h per (f,w)
__device__ float g_partial[16][3];     // per (b,f): [tsum, sum(tgtx), sum(tgty)]
__device__ uint2 g_meta[16][HH*3];     // per (b,f,row,chunk): {tmask bits, vpad bits}

__device__ __forceinline__ float tanh_hw(float x) {
    float y;
    asm("tanh.approx.f32 %0, %1;" : "=f"(y) : "f"(x));
    return y;
}
__device__ __forceinline__ float sigmoid_hw(float x) {
    return fmaf(0.5f, tanh_hw(0.5f * x), 0.5f);
}
__device__ __forceinline__ float sigmoid_fast(float x) {   // exact version (epilogue)
    float a = fabsf(x);
    float u = __expf(-a);
    float r = __fdividef(1.0f, 1.0f + u);
    return (x >= 0.0f) ? r : u * r;
}

__device__ __forceinline__ float warp_sum(float v) {
    #pragma unroll
    for (int o = 16; o; o >>= 1) v += __shfl_xor_sync(0xffffffff, v, o);
    return v;
}
__device__ __forceinline__ float warp_max(float v) {
    #pragma unroll
    for (int o = 16; o; o >>= 1) v = fmaxf(v, __shfl_xor_sync(0xffffffff, v, o));
    return v;
}

// ---------------------------------------------------------------------------
// Prep: one block per (b,f). 384 threads = 12 warps; warp owns 8 rows.
// ---------------------------------------------------------------------------
__global__ __launch_bounds__(384) void prep_kernel(
    const float* __restrict__ tmask, const unsigned char* __restrict__ vpad)
{
    int bf = blockIdx.x;            // 0..15
    int b = bf >> 3, f = bf & 7;
    int tid = threadIdx.x;
    int wp = tid >> 5, lane = tid & 31;
    const float* base = tmask + (size_t)bf * HW;
    const unsigned char* vb = vpad + (size_t)b * HW;

    __shared__ float colPart[12][3][32];
    __shared__ float warpRM[12];
    __shared__ float warpTS[12];
    __shared__ float colFinal[96];

    float cm0 = -CUDART_INF_F, cm1 = -CUDART_INF_F, cm2 = -CUDART_INF_F;
    float rm_sum = 0.0f, t_sum = 0.0f;

    #pragma unroll 2
    for (int r = 0; r < 8; ++r) {
        int row = wp * 8 + r;
        const float* rp = base + row * WW;
        const unsigned char* vr = vb + row * WW;
        float v0 = rp[lane], v1 = rp[32 + lane], v2 = rp[64 + lane];
        unsigned char q0 = vr[lane], q1 = vr[32 + lane], q2 = vr[64 + lane];
        unsigned t0 = __ballot_sync(0xffffffff, v0 != 0.0f);
        unsigned t1 = __ballot_sync(0xffffffff, v1 != 0.0f);
        unsigned t2 = __ballot_sync(0xffffffff, v2 != 0.0f);
        unsigned p0 = __ballot_sync(0xffffffff, q0 != 0);
        unsigned p1 = __ballot_sync(0xffffffff, q1 != 0);
        unsigned p2 = __ballot_sync(0xffffffff, q2 != 0);
        if (lane == 0) {
            g_meta[bf][row * 3 + 0] = make_uint2(t0, p0);
            g_meta[bf][row * 3 + 1] = make_uint2(t1, p1);
            g_meta[bf][row * 3 + 2] = make_uint2(t2, p2);
        }
        float rm = warp_max(fmaxf(fmaxf(v0, v1), v2));
        if (lane == 0) { g_tgtx[b][f * HH + row] = rm; rm_sum += rm; }
        t_sum += v0 + v1 + v2;
        cm0 = fmaxf(cm0, v0); cm1 = fmaxf(cm1, v1); cm2 = fmaxf(cm2, v2);
    }
    colPart[wp][0][lane] = cm0;
    colPart[wp][1][lane] = cm1;
    colPart[wp][2][lane] = cm2;
    float ts = warp_sum(t_sum);
    if (lane == 0) { warpTS[wp] = ts; warpRM[wp] = rm_sum; }
    __syncthreads();

    if (tid < 96) {
        int c = tid >> 5, l = tid & 31;
        float m = -CUDART_INF_F;
        #pragma unroll
        for (int w = 0; w < 12; ++w) m = fmaxf(m, colPart[w][c][l]);
        g_tgty[b][f * WW + tid] = m;
        colFinal[tid] = m;
    }
    __syncthreads();
    if (tid == 0) {
        float tsum = 0, txs = 0, tys = 0;
        #pragma unroll
        for (int i = 0; i < 12; ++i) { tsum += warpTS[i]; txs += warpRM[i]; }
        for (int i = 0; i < 96; ++i) tys += colFinal[i];
        g_partial[bf][0] = tsum; g_partial[bf][1] = txs; g_partial[bf][2] = tys;
    }
}

// ---------------------------------------------------------------------------
// Main cost kernel: one block per (b, q). 384 threads = 12 warps, occ 3.
// Warp wp owns rows 8*wp..8*wp+7 of every frame; lane l covers cols {l,32+l,64+l}.
// ---------------------------------------------------------------------------
__global__ __launch_bounds__(384, 3) void cost_kernel(
    const float* __restrict__ logits,   // (2,8,300,1)
    const float* __restrict__ boxes,    // (2,8,300,4)
    const float* __restrict__ masks,    // (2,8,300,96,96)
    const float* __restrict__ tbox,     // (2,8,4)
    const int*   __restrict__ tvalid,   // (2,8)
    float* __restrict__ C)              // (2,300)
{
    int blk = blockIdx.x;
    int b = blk / NQ, q = blk % NQ;
    int tid = threadIdx.x;
    int warp = tid >> 5, lane = tid & 31;

    __shared__ float rowFinal[NF * HH];           // 3 KB
    __shared__ float colAll[NF * 3 * 384];        // 36 KB: [f][chunk][warp][lane]
    __shared__ float red[12][7];

    float facc = 0.0f, nacc = 0.0f, sacc = 0.0f;

    for (int f = 0; f < NF; ++f) {
        const float* mb = masks + (size_t)((b * NF + f) * NQ + q) * HW + lane;
        const uint2* mt = g_meta[b * NF + f];
        float c0 = -CUDART_INF_F, c1 = -CUDART_INF_F, c2 = -CUDART_INF_F;
        #pragma unroll 2
        for (int r = 0; r < 8; ++r) {
            int row = warp * 8 + r;
            uint2 m0 = mt[row * 3 + 0];
            uint2 m1 = mt[row * 3 + 1];
            uint2 m2 = mt[row * 3 + 2];
            const float* rp = mb + row * WW;
            float x0 = rp[0], x1 = rp[32], x2 = rp[64];
            if ((m0.y >> lane) & 1) x0 = 0.0f;
            if ((m1.y >> lane) & 1) x1 = 0.0f;
            if ((m2.y >> lane) & 1) x2 = 0.0f;

            #pragma unroll
            for (int c = 0; c < 3; ++c) {
                float x = (c == 0) ? x0 : (c == 1) ? x1 : x2;
                unsigned tw = (c == 0) ? m0.x : (c == 1) ? m1.x : m2.x;
                bool tb = (tw >> lane) & 1;
                float p = sigmoid_hw(x);                 // 1 MUFU
                float omp_ = 1.0f - p;
                float pa = fmaxf(p, omp_);               // sigmoid(|x|)
                float lg = -__logf(pa);                  // log1p(exp(-|x|)), 1 MUFU
                float ce = fmaxf(tb ? -x : x, 0.0f) + lg;
                float omp = tb ? omp_ : p;               // 1 - p_t
                float at = tb ? 0.25f : 0.75f;
                facc = fmaf(at * ce * omp, omp, facc);
                sacc += p;
                if (tb) nacc += p;
            }
            c0 = fmaxf(c0, x0); c1 = fmaxf(c1, x1); c2 = fmaxf(c2, x2);
            float rm = warp_max(fmaxf(fmaxf(x0, x1), x2));
            if (lane == 0) rowFinal[f * HH + row] = rm;
        }
        colAll[((f * 3 + 0) * 12 + warp) * 32 + lane] = c0;
        colAll[((f * 3 + 1) * 12 + warp) * 32 + lane] = c1;
        colAll[((f * 3 + 2) * 12 + warp) * 32 + lane] = c2;
    }
    __syncthreads();

    // projection dice partials: 768 rows + 768 cols, 2 each per thread
    float sx = 0, nx = 0, sy = 0, ny = 0;
    #pragma unroll
    for (int j = tid; j < NF * HH; j += 384) {
        float px = sigmoid_fast(rowFinal[j]);
        sx += px; nx += px * g_tgtx[b][j];
        int f = j / WW, w = j % WW;
        int c = w >> 5, l = w & 31;
        const float* cp = &colAll[((f * 3 + c) * 12) * 32 + l];
        float m = cp[0];
        #pragma unroll
        for (int wp = 1; wp < 12; ++wp) m = fmaxf(m, cp[wp * 32]);
        float py = sigmoid_fast(m);
        sy += py; ny += py * g_tgty[b][j];
    }

    float v0 = warp_sum(facc), v1 = warp_sum(nacc), v2 = warp_sum(sacc);
    float v3 = warp_sum(sx),   v4 = warp_sum(nx);
    float v5 = warp_sum(sy),   v6 = warp_sum(ny);
    if (lane == 0) {
        red[warp][0] = v0; red[warp][1] = v1; red[warp][2] = v2;
        red[warp][3] = v3; red[warp][4] = v4; red[warp][5] = v5; red[warp][6] = v6;
    }
    __syncthreads();

    if (tid == 0) {
        float t0=0,t1=0,t2=0,t3=0,t4=0,t5=0,t6=0;
        #pragma unroll
        for (int i = 0; i < 12; ++i) {
            t0 += red[i][0]; t1 += red[i][1]; t2 += red[i][2];
            t3 += red[i][3]; t4 += red[i][4]; t5 += red[i][5]; t6 += red[i][6];
        }
        float tsum = 0, txs = 0, tys = 0;
        #pragma unroll
        for (int f = 0; f < NF; ++f) {
            tsum += g_partial[b * NF + f][0];
            txs  += g_partial[b * NF + f][1];
            tys  += g_partial[b * NF + f][2];
        }
        float cost_mask = t0 / (float)FHW;
        float cost_dice = -((2.0f * t1 + 1.0f) / (t2 + tsum + 1.0f));
        float dx = (2.0f * t4 + 1.0f) / (t3 + txs + 1.0f);
        float dy = (2.0f * t6 + 1.0f) / (t5 + tys + 1.0f);
        float cost_proj = -0.5f * (dy + dx);

        float cls = 0, wsum = 0, bbox = 0, giou = 0;
        #pragma unroll
        for (int f = 0; f < NF; ++f) {
            float lg = logits[(b * NF + f) * NQ + q];
            float p = sigmoid_fast(lg);
            float neg = (1.0f - ALPHA_C) * p * p * (-__logf(1.0f - p + EPSV));
            float pos = ALPHA_C * (1.0f - p) * (1.0f - p) * (-__logf(p + EPSV));
            float wv = (tvalid[b * NF + f] != 0) ? 1.0f : 0.0f;
            cls += (pos - neg) * wv; wsum += wv;

            const float* bx = boxes + (size_t)((b * NF + f) * NQ + q) * 4;
            const float* tx = tbox + (size_t)(b * NF + f) * 4;
            bbox += fabsf(bx[0]-tx[0]) + fabsf(bx[1]-tx[1]) + fabsf(bx[2]-tx[2]) + fabsf(bx[3]-tx[3]);

            float sx0 = bx[0]-0.5f*bx[2], sy0 = bx[1]-0.5f*bx[3];
            float sx1 = bx[0]+0.5f*bx[2], sy1 = bx[1]+0.5f*bx[3];
            float tx0 = tx[0]-0.5f*tx[2], ty0 = tx[1]-0.5f*tx[3];
            float tx1 = tx[0]+0.5f*tx[2], ty1 = tx[1]+0.5f*tx[3];
            float a1 = (sx1-sx0)*(sy1-sy0);
            float a2 = (tx1-tx0)*(ty1-ty0);
            float iw = fmaxf(fminf(sx1,tx1) - fmaxf(sx0,tx0), 0.0f);
            float ih = fmaxf(fminf(sy1,ty1) - fmaxf(sy0,ty0), 0.0f);
            float inter = iw * ih;
            float uni = a1 + a2 - inter;
            float iou = inter / uni;
            float cw = fmaxf(fmaxf(sx1,tx1) - fminf(sx0,tx0), 0.0f);
            float ch = fmaxf(fmaxf(sy1,ty1) - fminf(sy0,ty0), 0.0f);
            float ac = cw * ch;
            giou += -(iou - (ac - uni) / ac);
        }
        float cost_class = cls / wsum;
        float cost_bbox  = bbox * (1.0f / NF);
        float cost_giou  = giou * (1.0f / NF);

        C[b * NQ + q] = cost_class + cost_bbox + cost_giou + cost_mask + cost_dice + cost_proj;
    }
}

// ---------------------------------------------------------------------------
// Argmin over queries per batch + tail writes. grid=2, block=256
// ---------------------------------------------------------------------------
__global__ void argmin_kernel(const float* __restrict__ C, float* __restrict__ out, int out_size) {
    int b = blockIdx.x;
    int tid = threadIdx.x;
    float best = CUDART_INF_F; int bi = NQ;
    for (int q = tid; q < NQ; q += blockDim.x) {
        float v = C[b * NQ + q];
        if (v < best || (v == best && q < bi)) { best = v; bi = q; }
    }
    #pragma unroll
    for (int o = 16; o; o >>= 1) {
        float ov = __shfl_down_sync(0xffffffff, best, o);
        int   oi = __shfl_down_sync(0xffffffff, bi,   o);
        if (ov < best || (ov == best && oi < bi)) { best = ov; bi = oi; }
    }
    __shared__ float sv[8]; __shared__ int si[8];
    int wid = tid >> 5, lane = tid & 31;
    if (lane == 0) { sv[wid] = best; si[wid] = bi; }
    __syncthreads();
    if (tid == 0) {
        int nw = blockDim.x >> 5;
        for (int i = 1; i < nw; ++i) {
            if (sv[i] < best || (sv[i] == best && si[i] < bi)) { best = sv[i]; bi = si[i]; }
        }
        if (out_size >= 608) {
            long long* op = (long long*)(out + 600);
            op[b] = (long long)bi;
            op[2 + b] = 0ll;
            if (b == 0) for (int i = 608; i < out_size; ++i) out[i] = 0.0f;
        } else if (out_size >= 604) {
            out[600 + b] = (float)bi;
            out[602 + b] = 0.0f;
            if (b == 0) for (int i = 604; i < out_size; ++i) out[i] = 0.0f;
        } else {
            if (b == 0) for (int i = 600; i < out_size; ++i) out[i] = 0.0f;
        }
    }
}

extern "C" void kernel_launch(void* const* d_in, const int* in_sizes, int n_in,
                              void* d_out, int out_size) {
    const float* logits = (const float*)d_in[0];
    const float* boxes  = (const float*)d_in[1];
    const float* masks  = (const float*)d_in[2];
    const float* tmask  = (const float*)d_in[3];
    const float* tbox   = (const float*)d_in[4];
    const int*   tvalid = (const int*)d_in[5];
    const unsigned char* vpad = (const unsigned char*)d_in[6];
    float* out = (float*)d_out;

    prep_kernel<<<16, 384>>>(tmask, vpad);
    cost_kernel<<<2 * NQ, 384>>>(logits, boxes, masks, tbox, tvalid, out);
    argmin_kernel<<<2, 256>>>(out, out, out_size);
}